// round 1
// baseline (speedup 1.0000x reference)
#include <cuda_runtime.h>
#include <cuda_bf16.h>
#include <math.h>

// Problem constants
#define NB 32      // batch
#define CC 512     // channels
#define HH 64
#define WW 64
#define HWP 4096   // H*W
#define CB 32      // bottleneck channels
#define EPS 1e-5f

// Scratch (allocation-free rule: __device__ globals)
__device__ __align__(16) float g_logits[NB * HWP];   // logits -> attn (in place)
__device__ __align__(16) float g_ctx[NB * CC];
__device__ __align__(16) float g_vout[NB * CC];

// ---------------------------------------------------------------------------
// K1: logits[n,h,w] = sum_c x[n,c,h,w]*wk[c] + wk_b
// float4 over w; one thread handles 4 pixels across all 512 channels.
// grid: 256 blocks x 128 threads = 32768 threads = NB*HWP/4
// ---------------------------------------------------------------------------
__global__ void k_logits(const float* __restrict__ x,
                         const float* __restrict__ wk,
                         const float* __restrict__ wkb) {
    __shared__ float swk[CC];
    for (int i = threadIdx.x; i < CC; i += blockDim.x) swk[i] = wk[i];
    __syncthreads();

    int tid = blockIdx.x * blockDim.x + threadIdx.x;     // 0 .. 32767
    int n = tid >> 10;                                   // /1024 (vec4 per plane)
    int p = tid & 1023;                                  // vec4 index in plane

    const float4* xp = reinterpret_cast<const float4*>(x) + (size_t)n * CC * 1024 + p;
    float b = wkb[0];
    float4 acc = make_float4(b, b, b, b);

#pragma unroll 8
    for (int c = 0; c < CC; c++) {
        float4 v = xp[(size_t)c * 1024];
        float w = swk[c];
        acc.x = fmaf(v.x, w, acc.x);
        acc.y = fmaf(v.y, w, acc.y);
        acc.z = fmaf(v.z, w, acc.z);
        acc.w = fmaf(v.w, w, acc.w);
    }
    reinterpret_cast<float4*>(g_logits)[tid] = acc;
}

// ---------------------------------------------------------------------------
// K2: softmax over H (axis=1 of (n,h,w)), in place on g_logits.
// grid: 32 (n), block: 64 (w). Each thread owns one (n, w) column of 64.
// ---------------------------------------------------------------------------
__global__ void k_softmax(void) {
    int n = blockIdx.x;
    int w = threadIdx.x;
    float* base = g_logits + n * HWP + w;

    float mx = -INFINITY;
#pragma unroll
    for (int h = 0; h < HH; h++) mx = fmaxf(mx, base[h * WW]);

    float s = 0.f;
#pragma unroll
    for (int h = 0; h < HH; h++) {
        float e = expf(base[h * WW] - mx);
        base[h * WW] = e;
        s += e;
    }
    float inv = 1.f / s;
#pragma unroll
    for (int h = 0; h < HH; h++) base[h * WW] *= inv;
}

// ---------------------------------------------------------------------------
// K3: ctx[n,c] = sum_{h,w} x[n,c,h,w] * attn[n,h,w]
// grid: NB*CC blocks, 128 threads; each block reduces one 4096-elem plane.
// attn (16KB per image) is L2-resident across the 512 blocks of an image.
// ---------------------------------------------------------------------------
__global__ void k_ctx(const float* __restrict__ x) {
    int nc = blockIdx.x;
    int n = nc >> 9;  // /512

    const float4* xp = reinterpret_cast<const float4*>(x) + (size_t)nc * 1024;
    const float4* ap = reinterpret_cast<const float4*>(g_logits) + (size_t)n * 1024;

    float s = 0.f;
    for (int i = threadIdx.x; i < 1024; i += 128) {
        float4 xv = xp[i];
        float4 av = ap[i];
        s = fmaf(xv.x, av.x, s);
        s = fmaf(xv.y, av.y, s);
        s = fmaf(xv.z, av.z, s);
        s = fmaf(xv.w, av.w, s);
    }
    // warp reduce
#pragma unroll
    for (int o = 16; o; o >>= 1) s += __shfl_xor_sync(0xffffffffu, s, o);

    __shared__ float red[4];
    int wid = threadIdx.x >> 5;
    int lane = threadIdx.x & 31;
    if (lane == 0) red[wid] = s;
    __syncthreads();
    if (threadIdx.x == 0) {
        g_ctx[nc] = red[0] + red[1] + red[2] + red[3];
    }
}

// ---------------------------------------------------------------------------
// K4: per image: v = relu(LN(ctx @ wv1^T)) ; vout = v @ wv2^T
// grid: 32, block: 512.
// ---------------------------------------------------------------------------
__global__ void k_mlp(const float* __restrict__ wv1,
                      const float* __restrict__ lng,
                      const float* __restrict__ lnb,
                      const float* __restrict__ wv2) {
    int n = blockIdx.x;
    __shared__ float sctx[CC];
    __shared__ float sv[CB];

    sctx[threadIdx.x] = g_ctx[n * CC + threadIdx.x];
    __syncthreads();

    int wid = threadIdx.x >> 5;
    int lane = threadIdx.x & 31;

    // 16 warps compute 32 dot products (2 each)
    for (int j = wid; j < CB; j += 16) {
        const float* wrow = wv1 + j * CC;
        float p = 0.f;
        for (int c = lane; c < CC; c += 32) p = fmaf(sctx[c], wrow[c], p);
#pragma unroll
        for (int o = 16; o; o >>= 1) p += __shfl_xor_sync(0xffffffffu, p, o);
        if (lane == 0) sv[j] = p;
    }
    __syncthreads();

    // warp 0: LayerNorm over 32 values + ReLU
    if (wid == 0) {
        float v = sv[lane];
        float s = v;
#pragma unroll
        for (int o = 16; o; o >>= 1) s += __shfl_xor_sync(0xffffffffu, s, o);
        float mu = s * (1.f / CB);
        float d = v - mu;
        float q = d * d;
#pragma unroll
        for (int o = 16; o; o >>= 1) q += __shfl_xor_sync(0xffffffffu, q, o);
        float var = q * (1.f / CB);
        float r = d * rsqrtf(var + EPS) * lng[lane] + lnb[lane];
        sv[lane] = fmaxf(r, 0.f);
    }
    __syncthreads();

    // each of 512 threads computes one output channel
    const float* w2 = wv2 + threadIdx.x * CB;
    float o = 0.f;
#pragma unroll
    for (int j = 0; j < CB; j++) o = fmaf(sv[j], w2[j], o);
    g_vout[n * CC + threadIdx.x] = o;
}

// ---------------------------------------------------------------------------
// K5: out[n,c,h,w] = x[n,c,h,w] + vout[n,c]   (float4 grid-stride)
// ---------------------------------------------------------------------------
__global__ void k_out(const float* __restrict__ x, float* __restrict__ out) {
    const float4* xv = reinterpret_cast<const float4*>(x);
    float4* ov = reinterpret_cast<float4*>(out);
    size_t total = (size_t)NB * CC * HWP / 4;  // 16777216 vec4
    size_t stride = (size_t)gridDim.x * blockDim.x;
    for (size_t v = blockIdx.x * (size_t)blockDim.x + threadIdx.x; v < total; v += stride) {
        int nc = (int)(v >> 10);  // 1024 vec4 per (n,c) plane
        float add = __ldg(&g_vout[nc]);
        float4 t = xv[v];
        t.x += add; t.y += add; t.z += add; t.w += add;
        ov[v] = t;
    }
}

// ---------------------------------------------------------------------------
extern "C" void kernel_launch(void* const* d_in, const int* in_sizes, int n_in,
                              void* d_out, int out_size) {
    const float* x    = (const float*)d_in[0];
    const float* wk_w = (const float*)d_in[1];
    const float* wk_b = (const float*)d_in[2];
    const float* wv1  = (const float*)d_in[3];
    const float* ln_g = (const float*)d_in[4];
    const float* ln_b = (const float*)d_in[5];
    const float* wv2  = (const float*)d_in[6];
    float* out = (float*)d_out;

    k_logits<<<256, 128>>>(x, wk_w, wk_b);
    k_softmax<<<NB, WW>>>();
    k_ctx<<<NB * CC, 128>>>(x);
    k_mlp<<<NB, CC>>>(wv1, ln_g, ln_b, wv2);
    k_out<<<8192, 256>>>(x, out);
}

// round 3
// speedup vs baseline: 1.2892x; 1.2892x over previous
#include <cuda_runtime.h>
#include <cuda_bf16.h>
#include <math.h>

// Problem constants
#define NB 32      // batch
#define CC 512     // channels
#define HH 64
#define WW 64
#define HWP 4096   // H*W
#define CB 32      // bottleneck channels
#define EPS 1e-5f

#define CH_SPLIT 8
#define CH_PER   64   // 512 / 8

// Scratch (allocation-free rule: __device__ globals)
__device__ __align__(16) float g_part[CH_SPLIT][NB * HWP];  // 4 MB partial logits
__device__ __align__(16) float g_attn[NB * HWP];            // softmax result
__device__ __align__(16) float g_ctx[NB * CC];
__device__ __align__(16) float g_v[NB][CB];                 // relu(LN(ctx@wv1^T))
__device__ int g_cnt[NB];                                    // arrive counters (self-resetting)

// ---------------------------------------------------------------------------
// K1: partial logits. Channel dim split 8-ways for memory-level parallelism.
// grid = 1024 blocks (128 column-blocks x 8 chunks) x 256 threads.
// NOTE: wk_b dropped — softmax is invariant to a constant shift.
// NOTE: weights loaded SCALAR (input buffer only 4B-aligned after wk_b).
// ---------------------------------------------------------------------------
__global__ void k_logits(const float* __restrict__ x,
                         const float* __restrict__ wk) {
    __shared__ float swk[CH_PER];
    int chunk = blockIdx.x & 7;
    if (threadIdx.x < CH_PER) swk[threadIdx.x] = wk[chunk * CH_PER + threadIdx.x];
    __syncthreads();

    int colb = blockIdx.x >> 3;                       // 0..127
    int col  = colb * 256 + threadIdx.x;              // 0..32767 (vec4 columns)
    int n = col >> 10;
    int p = col & 1023;

    const float4* xp = reinterpret_cast<const float4*>(x)
                     + (size_t)n * CC * 1024 + (size_t)(chunk * CH_PER) * 1024 + p;
    float4 acc = make_float4(0.f, 0.f, 0.f, 0.f);

#pragma unroll 16
    for (int c = 0; c < CH_PER; c++) {
        float4 v = xp[(size_t)c * 1024];
        float w = swk[c];
        acc.x = fmaf(v.x, w, acc.x);
        acc.y = fmaf(v.y, w, acc.y);
        acc.z = fmaf(v.z, w, acc.z);
        acc.w = fmaf(v.w, w, acc.w);
    }
    reinterpret_cast<float4*>(g_part[chunk])[col] = acc;
}

// ---------------------------------------------------------------------------
// K2: sum 8 partials -> softmax over H per (n,w) column -> g_attn.
// grid = 32 (images), block = 256. Logits staged in SMEM (16 KB).
// ---------------------------------------------------------------------------
__global__ void k_softmax(void) {
    __shared__ float sl[HWP];
    int n = blockIdx.x;

    for (int i = threadIdx.x; i < 1024; i += 256) {
        float4 s = make_float4(0.f, 0.f, 0.f, 0.f);
#pragma unroll
        for (int k = 0; k < CH_SPLIT; k++) {
            float4 v = reinterpret_cast<const float4*>(g_part[k])[n * 1024 + i];
            s.x += v.x; s.y += v.y; s.z += v.z; s.w += v.w;
        }
        reinterpret_cast<float4*>(sl)[i] = s;
    }
    __syncthreads();

    if (threadIdx.x < WW) {
        int w = threadIdx.x;
        float mx = -INFINITY;
#pragma unroll
        for (int h = 0; h < HH; h++) mx = fmaxf(mx, sl[h * WW + w]);
        float s = 0.f;
#pragma unroll
        for (int h = 0; h < HH; h++) {
            float e = __expf(sl[h * WW + w] - mx);
            sl[h * WW + w] = e;
            s += e;
        }
        float inv = 1.f / s;
        float* dst = g_attn + n * HWP + w;
#pragma unroll
        for (int h = 0; h < HH; h++) dst[h * WW] = sl[h * WW + w] * inv;
    }
}

// ---------------------------------------------------------------------------
// K3: ctx[n,c] = sum_hw x*attn, one block per (n,c) plane.
// Fused tail: last-arriving block per image runs GEMM1 + LN + ReLU -> g_v[n].
// ---------------------------------------------------------------------------
__global__ void k_ctx(const float* __restrict__ x,
                      const float* __restrict__ wv1,
                      const float* __restrict__ lng,
                      const float* __restrict__ lnb) {
    int nc = blockIdx.x;
    int n = nc >> 9;

    const float4* xp = reinterpret_cast<const float4*>(x) + (size_t)nc * 1024;
    const float4* ap = reinterpret_cast<const float4*>(g_attn) + (size_t)n * 1024;

    float s = 0.f;
#pragma unroll 4
    for (int i = threadIdx.x; i < 1024; i += 128) {
        float4 xv = xp[i];
        float4 av = ap[i];
        s = fmaf(xv.x, av.x, s);
        s = fmaf(xv.y, av.y, s);
        s = fmaf(xv.z, av.z, s);
        s = fmaf(xv.w, av.w, s);
    }
#pragma unroll
    for (int o = 16; o; o >>= 1) s += __shfl_xor_sync(0xffffffffu, s, o);

    __shared__ float red[4];
    __shared__ int is_last;
    int wid = threadIdx.x >> 5;
    int lane = threadIdx.x & 31;
    if (lane == 0) red[wid] = s;
    __syncthreads();
    if (threadIdx.x == 0) {
        g_ctx[nc] = red[0] + red[1] + red[2] + red[3];
        __threadfence();
        int old = atomicAdd(&g_cnt[n], 1);
        is_last = (old == 511);
    }
    __syncthreads();
    if (!is_last) return;

    // ---- fused MLP stage 1 for image n (128 threads) ----
    __threadfence();  // acquire: see all g_ctx writes
    __shared__ float sctx[CC];
    __shared__ float sv[CB];
    for (int i = threadIdx.x; i < CC; i += 128) sctx[i] = g_ctx[n * CC + i];
    __syncthreads();

    // 4 warps x 8 rows each: v[j] = dot(ctx, wv1[j,:])  (SCALAR weight loads!)
    for (int j = wid; j < CB; j += 4) {
        const float* wr = wv1 + j * CC;
        float p = 0.f;
#pragma unroll
        for (int k = 0; k < 16; k++) {
            int c = lane + k * 32;
            p = fmaf(__ldg(&wr[c]), sctx[c], p);
        }
#pragma unroll
        for (int o = 16; o; o >>= 1) p += __shfl_xor_sync(0xffffffffu, p, o);
        if (lane == 0) sv[j] = p;
    }
    __syncthreads();

    // warp 0: LayerNorm over 32 + ReLU -> g_v
    if (wid == 0) {
        float v = sv[lane];
        float m = v;
#pragma unroll
        for (int o = 16; o; o >>= 1) m += __shfl_xor_sync(0xffffffffu, m, o);
        float mu = m * (1.f / CB);
        float d = v - mu;
        float q = d * d;
#pragma unroll
        for (int o = 16; o; o >>= 1) q += __shfl_xor_sync(0xffffffffu, q, o);
        float var = q * (1.f / CB);
        float r = d * rsqrtf(var + EPS) * lng[lane] + lnb[lane];
        g_v[n][lane] = fmaxf(r, 0.f);
        if (lane == 0) g_cnt[n] = 0;   // reset for next graph replay
    }
}

// ---------------------------------------------------------------------------
// K5: out = x + vout broadcast. GEMM2 fused: each block computes the 2
// per-plane dots vout[n,c] = dot(g_v[n,:], wv2[c,:]) it needs.
// grid = 8192 x 256; each block covers exactly 2 (n,c) planes (2048 vec4).
// ---------------------------------------------------------------------------
__global__ void k_out(const float* __restrict__ x,
                      const float* __restrict__ wv2,
                      float* __restrict__ out) {
    __shared__ float sadd[2];
    int b = blockIdx.x;
    int plane0 = b * 2;

    if (threadIdx.x < 64) {
        int which = threadIdx.x >> 5;
        int lane = threadIdx.x & 31;
        int nc = plane0 + which;
        int n = nc >> 9;
        int c = nc & 511;
        float p = g_v[n][lane] * __ldg(&wv2[c * CB + lane]);   // scalar load
#pragma unroll
        for (int o = 16; o; o >>= 1) p += __shfl_xor_sync(0xffffffffu, p, o);
        if (lane == 0) sadd[which] = p;
    }
    __syncthreads();

    const float4* xv = reinterpret_cast<const float4*>(x);
    float4* ov = reinterpret_cast<float4*>(out);
    size_t base = (size_t)b * 2048;
#pragma unroll
    for (int i = 0; i < 8; i++) {
        int local = threadIdx.x + i * 256;
        float add = sadd[local >> 10];
        float4 t = xv[base + local];
        t.x += add; t.y += add; t.z += add; t.w += add;
        ov[base + local] = t;
    }
}

// ---------------------------------------------------------------------------
extern "C" void kernel_launch(void* const* d_in, const int* in_sizes, int n_in,
                              void* d_out, int out_size) {
    const float* x    = (const float*)d_in[0];
    const float* wk_w = (const float*)d_in[1];
    // d_in[2] = wk_b : unused (softmax shift-invariant)
    const float* wv1  = (const float*)d_in[3];
    const float* ln_g = (const float*)d_in[4];
    const float* ln_b = (const float*)d_in[5];
    const float* wv2  = (const float*)d_in[6];
    float* out = (float*)d_out;

    k_logits<<<1024, 256>>>(x, wk_w);
    k_softmax<<<NB, 256>>>();
    k_ctx<<<NB * CC, 128>>>(x, wv1, ln_g, ln_b);
    k_out<<<8192, 256>>>(x, wv2, out);
}